// round 3
// baseline (speedup 1.0000x reference)
#include <cuda_runtime.h>
#include <cuda_bf16.h>
#include <math.h>

#define N_USERS 100000
#define N_ITEMS 50000
#define N_NODES (N_USERS + N_ITEMS)
#define DIM 32
#define N_EDGES 2400000
#define K_STEPS 10

#define SCAN_BLOCK 1024
#define SCAN_NBLOCKS ((N_NODES + SCAN_BLOCK - 1) / SCAN_BLOCK)   // 147
#define DEG_BINS 256

// ---------------- device scratch (no allocations allowed) ----------------
__device__ float g_h[N_NODES * DIM];        // current state
__device__ float g_t[N_NODES * DIM];        // hop-1 result
__device__ float g_init[N_NODES * DIM];     // normalized static state
__device__ float g_alpha[N_NODES];          // sigmoid(alpha_logit)
__device__ int2  g_edges[N_EDGES];          // CSR payload: {src, w bits} grouped by dst
__device__ int   g_rowstart[N_NODES + 1];   // CSR row pointers (by dst)
__device__ int   g_cursor[N_NODES];         // counts, then scatter cursors
__device__ int   g_blocksums[SCAN_NBLOCKS];
__device__ int   g_blockoffs[SCAN_NBLOCKS + 1];
__device__ int   g_perm[N_NODES];           // nodes sorted by degree
__device__ int   g_dhist[DEG_BINS];         // degree histogram
__device__ int   g_dcur[DEG_BINS];          // scanned offsets / scatter cursors
__device__ unsigned g_maxbits;              // max row sumsq (bit-compare trick)

// ---------------- 1. zero counters ----------------
__global__ void zero_kernel() {
    int i = blockIdx.x * blockDim.x + threadIdx.x;
    if (i < N_NODES) g_cursor[i] = 0;
    if (i < DEG_BINS) g_dhist[i] = 0;
    if (i == 0) g_maxbits = 0u;
}

// ---------------- 2. max row-norm^2 (warp per node) ----------------
__global__ void norm_kernel(const float* __restrict__ xu, const float* __restrict__ xi) {
    int warp = (blockIdx.x * blockDim.x + threadIdx.x) >> 5;
    int lane = threadIdx.x & 31;
    if (warp >= N_NODES) return;
    const float* row = (warp < N_USERS) ? (xu + (size_t)warp * DIM)
                                        : (xi + (size_t)(warp - N_USERS) * DIM);
    float v = row[lane];
    float ss = v * v;
    #pragma unroll
    for (int d = 16; d; d >>= 1) ss += __shfl_xor_sync(0xFFFFFFFFu, ss, d);
    if (lane == 0) atomicMax(&g_maxbits, __float_as_uint(ss));  // ss >= 0: bit order == float order
}

// ---------------- 3. histogram of edge_dst ----------------
__global__ void count_kernel(const int* __restrict__ edge_dst) {
    int e = blockIdx.x * blockDim.x + threadIdx.x;
    if (e < N_EDGES) atomicAdd(&g_cursor[edge_dst[e]], 1);
}

// ---------------- 4a. per-block scan ----------------
__global__ void scanA_kernel() {
    __shared__ int warp_sums[32];
    int i = blockIdx.x * SCAN_BLOCK + threadIdx.x;
    int lane = threadIdx.x & 31, wid = threadIdx.x >> 5;
    int v = (i < N_NODES) ? g_cursor[i] : 0;
    int x = v;
    #pragma unroll
    for (int d = 1; d < 32; d <<= 1) {
        int t = __shfl_up_sync(0xFFFFFFFFu, x, d);
        if (lane >= d) x += t;
    }
    if (lane == 31) warp_sums[wid] = x;
    __syncthreads();
    if (wid == 0) {
        int y = warp_sums[lane];
        #pragma unroll
        for (int d = 1; d < 32; d <<= 1) {
            int t = __shfl_up_sync(0xFFFFFFFFu, y, d);
            if (lane >= d) y += t;
        }
        warp_sums[lane] = y;
    }
    __syncthreads();
    int warp_excl = (wid == 0) ? 0 : warp_sums[wid - 1];
    int incl = warp_excl + x;
    if (i < N_NODES) g_rowstart[i] = incl - v;   // block-local exclusive
    if (threadIdx.x == SCAN_BLOCK - 1) g_blocksums[blockIdx.x] = incl;
}

// ---------------- 4b. scan of block sums ----------------
__global__ void scanB_kernel() {
    __shared__ int sh[256];
    int t = threadIdx.x;
    int v = (t < SCAN_NBLOCKS) ? g_blocksums[t] : 0;
    sh[t] = v;
    __syncthreads();
    for (int d = 1; d < 256; d <<= 1) {
        int add = (t >= d) ? sh[t - d] : 0;
        __syncthreads();
        sh[t] += add;
        __syncthreads();
    }
    if (t < SCAN_NBLOCKS) g_blockoffs[t] = sh[t] - v;
    if (t == SCAN_NBLOCKS - 1) g_blockoffs[SCAN_NBLOCKS] = sh[t];
}

// ---------------- 4c. apply offsets ----------------
__global__ void scanC_kernel() {
    int i = blockIdx.x * blockDim.x + threadIdx.x;
    if (i < N_NODES) {
        int val = g_rowstart[i] + g_blockoffs[i / SCAN_BLOCK];
        g_rowstart[i] = val;
        g_cursor[i]   = val;
    }
    if (i == 0) g_rowstart[N_NODES] = g_blockoffs[SCAN_NBLOCKS];
}

// ---------------- 5. scatter edges into CSR buckets ----------------
__global__ void scatter_kernel(const int* __restrict__ edge_src,
                               const int* __restrict__ edge_dst,
                               const float* __restrict__ edge_w) {
    int e = blockIdx.x * blockDim.x + threadIdx.x;
    if (e >= N_EDGES) return;
    int dst = edge_dst[e];
    int p = atomicAdd(&g_cursor[dst], 1);
    g_edges[p] = make_int2(edge_src[e], __float_as_int(edge_w[e]));
}

// ---------------- 6a. degree histogram ----------------
__global__ void deghist_kernel() {
    int i = blockIdx.x * blockDim.x + threadIdx.x;
    if (i >= N_NODES) return;
    int d = g_rowstart[i + 1] - g_rowstart[i];
    if (d > DEG_BINS - 1) d = DEG_BINS - 1;
    atomicAdd(&g_dhist[d], 1);
}

// ---------------- 6b. scan degree bins (1 block of 256) ----------------
__global__ void degscan_kernel() {
    __shared__ int sh[DEG_BINS];
    int t = threadIdx.x;
    int v = g_dhist[t];
    sh[t] = v;
    __syncthreads();
    for (int d = 1; d < DEG_BINS; d <<= 1) {
        int add = (t >= d) ? sh[t - d] : 0;
        __syncthreads();
        sh[t] += add;
        __syncthreads();
    }
    g_dcur[t] = sh[t] - v;   // exclusive
}

// ---------------- 6c. scatter node ids into degree-sorted perm ----------------
__global__ void degscatter_kernel() {
    int i = blockIdx.x * blockDim.x + threadIdx.x;
    if (i >= N_NODES) return;
    int d = g_rowstart[i + 1] - g_rowstart[i];
    if (d > DEG_BINS - 1) d = DEG_BINS - 1;
    int p = atomicAdd(&g_dcur[d], 1);
    g_perm[p] = i;
}

// ---------------- 7. normalize state / static, sigmoid alpha ----------------
__global__ void init_kernel(const float* __restrict__ xu, const float* __restrict__ xi,
                            const float* __restrict__ su, const float* __restrict__ si,
                            const float* __restrict__ alpha_logit) {
    int idx = blockIdx.x * blockDim.x + threadIdx.x;
    if (idx < N_NODES * DIM) {
        float scale = rsqrtf(__uint_as_float(g_maxbits));
        float s, st;
        if (idx < N_USERS * DIM) { s = xu[idx]; st = su[idx]; }
        else                     { s = xi[idx - N_USERS * DIM]; st = si[idx - N_USERS * DIM]; }
        g_h[idx]    = s  * scale;
        g_init[idx] = st * scale;
    }
    if (idx < N_NODES) {
        g_alpha[idx] = 1.0f / (1.0f + expf(-alpha_logit[idx]));
    }
}

// ---------------- 8. propagation hop ----------------
// Half-warp per node (degree-sorted), float2 per lane, software-pipelined
// edge prefetch so the edge->gather dependency is pre-resolved.
template <bool UPDATE>
__global__ __launch_bounds__(256) void hop_kernel(const float2* __restrict__ in,
                                                  float2* __restrict__ out,
                                                  const float* __restrict__ dt) {
    int t = blockIdx.x * blockDim.x + threadIdx.x;
    int idx = t >> 4;             // half-warp per node
    int sub = t & 15;             // float2 slot within the 32-dim row
    if (idx >= N_NODES) return;
    int node = __ldg(&g_perm[idx]);
    int s = __ldg(&g_rowstart[node]);
    int e = __ldg(&g_rowstart[node + 1]);

    float ax0 = 0.f, ay0 = 0.f, ax1 = 0.f, ay1 = 0.f;
    int k = s;
    int2 e0, e1;
    if (k + 1 < e) { e0 = __ldg(&g_edges[k]); e1 = __ldg(&g_edges[k + 1]); }

    while (k + 3 < e) {
        int2 n0 = __ldg(&g_edges[k + 2]);   // prefetch next pair
        int2 n1 = __ldg(&g_edges[k + 3]);
        float2 v0 = __ldg(&in[e0.x * (DIM / 2) + sub]);
        float2 v1 = __ldg(&in[e1.x * (DIM / 2) + sub]);
        float w0 = __int_as_float(e0.y);
        float w1 = __int_as_float(e1.y);
        ax0 = fmaf(w0, v0.x, ax0); ay0 = fmaf(w0, v0.y, ay0);
        ax1 = fmaf(w1, v1.x, ax1); ay1 = fmaf(w1, v1.y, ay1);
        e0 = n0; e1 = n1; k += 2;
    }
    if (k + 1 < e) {                        // drain the prefetched pair
        float2 v0 = __ldg(&in[e0.x * (DIM / 2) + sub]);
        float2 v1 = __ldg(&in[e1.x * (DIM / 2) + sub]);
        float w0 = __int_as_float(e0.y);
        float w1 = __int_as_float(e1.y);
        ax0 = fmaf(w0, v0.x, ax0); ay0 = fmaf(w0, v0.y, ay0);
        ax1 = fmaf(w1, v1.x, ax1); ay1 = fmaf(w1, v1.y, ay1);
        k += 2;
    }
    if (k < e) {                            // odd tail
        int2 el = __ldg(&g_edges[k]);
        float2 v0 = __ldg(&in[el.x * (DIM / 2) + sub]);
        float w0 = __int_as_float(el.y);
        ax0 = fmaf(w0, v0.x, ax0); ay0 = fmaf(w0, v0.y, ay0);
    }
    float accx = ax0 + ax1, accy = ay0 + ay1;

    int oidx = node * (DIM / 2) + sub;
    if (UPDATE) {
        float step = __ldg(dt) * (1.0f / K_STEPS);
        float2 h   = ((const float2*)g_h)[oidx];
        float2 ini = ((const float2*)g_init)[oidx];
        float a    = __ldg(&g_alpha[node]);
        float2 r;
        r.x = h.x + step * (accx - a * h.x + ini.x);
        r.y = h.y + step * (accy - a * h.y + ini.y);
        out[oidx] = r;
    } else {
        float2 r; r.x = accx; r.y = accy;
        out[oidx] = r;
    }
}

// ---------------- launch ----------------
extern "C" void kernel_launch(void* const* d_in, const int* in_sizes, int n_in,
                              void* d_out, int out_size) {
    const float* xu          = (const float*)d_in[0];
    const float* xi          = (const float*)d_in[1];
    const float* su          = (const float*)d_in[2];
    const float* si          = (const float*)d_in[3];
    const float* edge_w      = (const float*)d_in[4];
    const float* alpha_logit = (const float*)d_in[5];
    const float* dt          = (const float*)d_in[6];
    const int*   edge_src    = (const int*)d_in[7];
    const int*   edge_dst    = (const int*)d_in[8];
    float*       out         = (float*)d_out;

    const int T = 256;
    const int nodeBlocks     = (N_NODES + T - 1) / T;
    const int warpNodeBlocks = (N_NODES * 32 + T - 1) / T;
    const int halfNodeBlocks = (N_NODES * 16 + T - 1) / T;
    const int edgeBlocks     = (N_EDGES + T - 1) / T;
    const int elemBlocks     = (N_NODES * DIM + T - 1) / T;

    zero_kernel<<<nodeBlocks, T>>>();
    norm_kernel<<<warpNodeBlocks, T>>>(xu, xi);
    count_kernel<<<edgeBlocks, T>>>(edge_dst);
    scanA_kernel<<<SCAN_NBLOCKS, SCAN_BLOCK>>>();
    scanB_kernel<<<1, 256>>>();
    scanC_kernel<<<nodeBlocks, T>>>();
    scatter_kernel<<<edgeBlocks, T>>>(edge_src, edge_dst, edge_w);
    deghist_kernel<<<nodeBlocks, T>>>();
    degscan_kernel<<<1, DEG_BINS>>>();
    degscatter_kernel<<<nodeBlocks, T>>>();
    init_kernel<<<elemBlocks, T>>>(xu, xi, su, si, alpha_logit);

    void* p_h = nullptr; void* p_t = nullptr;
    cudaGetSymbolAddress(&p_h, g_h);
    cudaGetSymbolAddress(&p_t, g_t);
    float2* fh = (float2*)p_h;
    float2* ft = (float2*)p_t;

    for (int step = 0; step < K_STEPS; step++) {
        hop_kernel<false><<<halfNodeBlocks, T>>>(fh, ft, dt);
        float2* dst2 = (step == K_STEPS - 1) ? (float2*)out : fh;
        hop_kernel<true><<<halfNodeBlocks, T>>>(ft, dst2, dt);
    }
}